// round 2
// baseline (speedup 1.0000x reference)
#include <cuda_runtime.h>
#include <cstdint>
#include <cstddef>

#define UNITS 512
#define VOCAB 32000
#define BATCH 128
#define SEQ   64

// ---------------- scratch (no allocation allowed) ----------------
__device__ float g_score[BATCH * SEQ];
__device__ float g_xc[BATCH * 2 * UNITS];        // [x (emb) | context]
__device__ float g_preact[BATCH * 3 * UNITS];    // xc @ gru_k + gru_b[0]
__device__ float g_y[BATCH * UNITS];             // relu(state @ dW + db)

// ---------------- tf32 helpers ----------------
__device__ __forceinline__ uint32_t f2tf32(float x) {
    uint32_t y;
    asm("cvt.rna.tf32.f32 %0, %1;" : "=r"(y) : "f"(x));
    return y;
}

__device__ __forceinline__ void mma8(float c[4], const uint32_t a[4],
                                     uint32_t b0, uint32_t b1) {
    asm volatile(
        "mma.sync.aligned.m16n8k8.row.col.f32.tf32.tf32.f32 "
        "{%0,%1,%2,%3}, {%4,%5,%6,%7}, {%8,%9}, {%0,%1,%2,%3};"
        : "+f"(c[0]), "+f"(c[1]), "+f"(c[2]), "+f"(c[3])
        : "r"(a[0]), "r"(a[1]), "r"(a[2]), "r"(a[3]), "r"(b0), "r"(b1));
}

// ---------------- generic 3xTF32 GEMM accumulate core ----------------
// acc += A(M_BLK x K) @ B(K x N_BLK), near-fp32 precision (hi/lo split).
// A row-major (lda), B row-major (ldb). Warp grid WM x WN; each warp owns
// MT m16 tiles x NT n8 tiles. KT=16 smem k-tiles.
template <int M_BLK, int N_BLK, int WM, int WN, int MT, int NT>
__device__ __forceinline__ void gemm_acc(const float* __restrict__ Ag, int lda,
                                         const float* __restrict__ Bg, int ldb,
                                         int K, float acc[MT][NT][4], float* sm) {
    constexpr int KT = 16;
    constexpr int SA = KT + 4;
    constexpr int SB = N_BLK + 4;
    constexpr int NTHR = WM * WN * 32;

    float* sAh = sm;
    float* sAl = sAh + M_BLK * SA;
    float* sBh = sAl + M_BLK * SA;
    float* sBl = sBh + KT * SB;

    const int tid  = threadIdx.x;
    const int lane = tid & 31;
    const int warp = tid >> 5;
    const int wm   = warp / WN;
    const int wn   = warp % WN;
    const int grp  = lane >> 2;   // A-row / B-col group
    const int qid  = lane & 3;    // A-col / B-row within k

    for (int k0 = 0; k0 < K; k0 += KT) {
        for (int i = tid; i < M_BLK * KT; i += NTHR) {
            int r = i / KT, c = i % KT;
            float v = Ag[(size_t)r * lda + k0 + c];
            float h = __uint_as_float(f2tf32(v));
            sAh[r * SA + c] = h;
            sAl[r * SA + c] = __uint_as_float(f2tf32(v - h));
        }
        for (int i = tid; i < KT * N_BLK; i += NTHR) {
            int r = i / N_BLK, c = i % N_BLK;
            float v = Bg[(size_t)(k0 + r) * ldb + c];
            float h = __uint_as_float(f2tf32(v));
            sBh[r * SB + c] = h;
            sBl[r * SB + c] = __uint_as_float(f2tf32(v - h));
        }
        __syncthreads();

        #pragma unroll
        for (int kk = 0; kk < KT; kk += 8) {
            uint32_t ah[MT][4], al[MT][4];
            #pragma unroll
            for (int mt = 0; mt < MT; mt++) {
                int r = (wm * MT + mt) * 16 + grp;
                int c = kk + qid;
                ah[mt][0] = __float_as_uint(sAh[r * SA + c]);
                ah[mt][1] = __float_as_uint(sAh[(r + 8) * SA + c]);
                ah[mt][2] = __float_as_uint(sAh[r * SA + c + 4]);
                ah[mt][3] = __float_as_uint(sAh[(r + 8) * SA + c + 4]);
                al[mt][0] = __float_as_uint(sAl[r * SA + c]);
                al[mt][1] = __float_as_uint(sAl[(r + 8) * SA + c]);
                al[mt][2] = __float_as_uint(sAl[r * SA + c + 4]);
                al[mt][3] = __float_as_uint(sAl[(r + 8) * SA + c + 4]);
            }
            #pragma unroll
            for (int nt = 0; nt < NT; nt++) {
                int bc = (wn * NT + nt) * 8 + grp;
                int br = kk + qid;
                uint32_t bh0 = __float_as_uint(sBh[br * SB + bc]);
                uint32_t bh1 = __float_as_uint(sBh[(br + 4) * SB + bc]);
                uint32_t bl0 = __float_as_uint(sBl[br * SB + bc]);
                uint32_t bl1 = __float_as_uint(sBl[(br + 4) * SB + bc]);
                #pragma unroll
                for (int mt = 0; mt < MT; mt++) {
                    mma8(acc[mt][nt], ah[mt], bh0, bh1);  // hi*hi
                    mma8(acc[mt][nt], al[mt], bh0, bh1);  // lo*hi
                    mma8(acc[mt][nt], ah[mt], bl0, bl1);  // hi*lo
                }
            }
        }
        __syncthreads();
    }
}

// ---------------- kernel 1: fused attention-score GEMM ----------------
// score[b,s] = sum_j tanh( (attn[b] @ W0)[s,j] + b0[j] + b1[j] ) * vW[j]
// Loops over 2 N-chunks of 256 so smem stays under the default 48 KB.
__global__ void __launch_bounds__(512) k_score(const float* __restrict__ attn,
                                               const float* __restrict__ W0,
                                               const float* __restrict__ b0,
                                               const float* __restrict__ b1,
                                               const float* __restrict__ vW) {
    extern __shared__ float sm[];
    constexpr int M_BLK = 64, N_BLK = 256, WM = 2, WN = 8, MT = 2, NT = 4;
    constexpr int GEMM_SM = 2 * M_BLK * 20 + 2 * 16 * (N_BLK + 4); // floats

    const int b = blockIdx.x;
    float* sScore = sm + GEMM_SM;
    if (threadIdx.x < SEQ) sScore[threadIdx.x] = 0.f;
    __syncthreads();

    const int lane = threadIdx.x & 31, warp = threadIdx.x >> 5;
    const int wm = warp / WN, wn = warp % WN;

    for (int nc = 0; nc < UNITS / N_BLK; nc++) {
        float acc[MT][NT][4] = {};
        gemm_acc<M_BLK, N_BLK, WM, WN, MT, NT>(
            attn + (size_t)b * SEQ * UNITS, UNITS,
            W0 + nc * N_BLK, UNITS, UNITS, acc, sm);

        #pragma unroll
        for (int mt = 0; mt < MT; mt++) {
            float rs0 = 0.f, rs1 = 0.f;
            #pragma unroll
            for (int nt = 0; nt < NT; nt++) {
                int c0 = nc * N_BLK + (wn * NT + nt) * 8 + (lane & 3) * 2;
                float bia0 = b0[c0] + b1[c0];
                float bia1 = b0[c0 + 1] + b1[c0 + 1];
                float v0 = vW[c0], v1 = vW[c0 + 1];
                rs0 += tanhf(acc[mt][nt][0] + bia0) * v0 + tanhf(acc[mt][nt][1] + bia1) * v1;
                rs1 += tanhf(acc[mt][nt][2] + bia0) * v0 + tanhf(acc[mt][nt][3] + bia1) * v1;
            }
            rs0 += __shfl_xor_sync(0xffffffffu, rs0, 1);
            rs0 += __shfl_xor_sync(0xffffffffu, rs0, 2);
            rs1 += __shfl_xor_sync(0xffffffffu, rs1, 1);
            rs1 += __shfl_xor_sync(0xffffffffu, rs1, 2);
            if ((lane & 3) == 0) {
                int r0 = (wm * MT + mt) * 16 + (lane >> 2);
                atomicAdd(&sScore[r0], rs0);
                atomicAdd(&sScore[r0 + 8], rs1);
            }
        }
        __syncthreads();
    }
    if (threadIdx.x < SEQ) g_score[b * SEQ + threadIdx.x] = sScore[threadIdx.x];
}

// ---------------- kernel 2: softmax + context + embedding gather ------
__global__ void __launch_bounds__(256) k_softmax_ctx(const float* __restrict__ attn,
                                                     const int* __restrict__ inputs,
                                                     const float* __restrict__ emb,
                                                     float* __restrict__ alpha_out) {
    __shared__ float sA[SEQ];
    __shared__ float sRed;
    const int b = blockIdx.x, tid = threadIdx.x;

    if (tid < SEQ) sA[tid] = g_score[b * SEQ + tid];
    __syncthreads();
    if (tid == 0) {
        float m = sA[0];
        for (int i = 1; i < SEQ; i++) m = fmaxf(m, sA[i]);
        sRed = m;
    }
    __syncthreads();
    if (tid < SEQ) sA[tid] = expf(sA[tid] - sRed);
    __syncthreads();
    if (tid == 0) {
        float s = 0.f;
        for (int i = 0; i < SEQ; i++) s += sA[i];
        sRed = s;
    }
    __syncthreads();
    if (tid < SEQ) {
        sA[tid] = sA[tid] / sRed;
        alpha_out[b * SEQ + tid] = sA[tid];
    }
    __syncthreads();

    const int idx = inputs[b];
    for (int u = tid; u < UNITS; u += 256) {
        float accv = 0.f;
        const float* ap = attn + (size_t)b * SEQ * UNITS + u;
        #pragma unroll 8
        for (int s = 0; s < SEQ; s++) accv += sA[s] * ap[s * UNITS];
        g_xc[b * 2 * UNITS + UNITS + u] = accv;                     // context
        g_xc[b * 2 * UNITS + u] = emb[(size_t)idx * UNITS + u];     // emb gather
    }
}

// ---------------- kernel 3: GRU input GEMM ----------------
// preact = xc @ gru_k + gru_b[0]   (128 x 1536)
__global__ void __launch_bounds__(256) k_gru_gemm(const float* __restrict__ gru_k,
                                                  const float* __restrict__ gru_b) {
    extern __shared__ float sm[];
    constexpr int M_BLK = 32, N_BLK = 128, WM = 2, WN = 4, MT = 1, NT = 4;
    float acc[MT][NT][4] = {};
    const int mb = blockIdx.x, nb = blockIdx.y;
    gemm_acc<M_BLK, N_BLK, WM, WN, MT, NT>(
        g_xc + (size_t)mb * M_BLK * 2 * UNITS, 2 * UNITS,
        gru_k + nb * N_BLK, 3 * UNITS, 2 * UNITS, acc, sm);

    const int lane = threadIdx.x & 31, warp = threadIdx.x >> 5;
    const int wm = warp / WN, wn = warp % WN;
    #pragma unroll
    for (int mt = 0; mt < MT; mt++) {
        int r0 = mb * M_BLK + (wm * MT + mt) * 16 + (lane >> 2);
        #pragma unroll
        for (int nt = 0; nt < NT; nt++) {
            int cg = nb * N_BLK + (wn * NT + nt) * 8 + (lane & 3) * 2;
            g_preact[r0 * 3 * UNITS + cg]           = acc[mt][nt][0] + gru_b[cg];
            g_preact[r0 * 3 * UNITS + cg + 1]       = acc[mt][nt][1] + gru_b[cg + 1];
            g_preact[(r0 + 8) * 3 * UNITS + cg]     = acc[mt][nt][2] + gru_b[cg];
            g_preact[(r0 + 8) * 3 * UNITS + cg + 1] = acc[mt][nt][3] + gru_b[cg + 1];
        }
    }
}

// ---------------- kernel 4: GRU gate combine (h == 0) ----------------
__global__ void __launch_bounds__(512) k_gates(const float* __restrict__ gru_b,
                                               float* __restrict__ state) {
    const int b = blockIdx.x, u = threadIdx.x;
    const float* p = g_preact + b * 3 * UNITS;
    const float* gb1 = gru_b + 3 * UNITS;   // gru_b[1]
    float xz = p[u], xr = p[UNITS + u], xh = p[2 * UNITS + u];
    float z = 1.f / (1.f + expf(-(xz + gb1[u])));
    float r = 1.f / (1.f + expf(-(xr + gb1[UNITS + u])));
    float hh = tanhf(xh + r * gb1[2 * UNITS + u]);
    state[b * UNITS + u] = (1.f - z) * hh;   // z*h term vanishes (h==0)
}

// ---------------- kernel 5: dense layer ----------------
// y = relu(state @ dW + db)
__global__ void __launch_bounds__(256) k_dense(const float* __restrict__ state,
                                               const float* __restrict__ dW,
                                               const float* __restrict__ db) {
    extern __shared__ float sm[];
    constexpr int M_BLK = 32, N_BLK = 128, WM = 2, WN = 4, MT = 1, NT = 4;
    float acc[MT][NT][4] = {};
    const int mb = blockIdx.x, nb = blockIdx.y;
    gemm_acc<M_BLK, N_BLK, WM, WN, MT, NT>(
        state + (size_t)mb * M_BLK * UNITS, UNITS,
        dW + nb * N_BLK, UNITS, UNITS, acc, sm);

    const int lane = threadIdx.x & 31, warp = threadIdx.x >> 5;
    const int wm = warp / WN, wn = warp % WN;
    #pragma unroll
    for (int mt = 0; mt < MT; mt++) {
        int r0 = mb * M_BLK + (wm * MT + mt) * 16 + (lane >> 2);
        #pragma unroll
        for (int nt = 0; nt < NT; nt++) {
            int cg = nb * N_BLK + (wn * NT + nt) * 8 + (lane & 3) * 2;
            g_y[r0 * UNITS + cg]           = fmaxf(acc[mt][nt][0] + db[cg], 0.f);
            g_y[r0 * UNITS + cg + 1]       = fmaxf(acc[mt][nt][1] + db[cg + 1], 0.f);
            g_y[(r0 + 8) * UNITS + cg]     = fmaxf(acc[mt][nt][2] + db[cg], 0.f);
            g_y[(r0 + 8) * UNITS + cg + 1] = fmaxf(acc[mt][nt][3] + db[cg + 1], 0.f);
        }
    }
}

// ---------------- kernel 6: vocab projection ----------------
// logits = y @ oW + ob   (128 x 32000). Full batch per block so each oW
// column strip streams from DRAM exactly once (65.5 MB total).
__global__ void __launch_bounds__(512) k_logits(const float* __restrict__ oW,
                                                const float* __restrict__ ob,
                                                float* __restrict__ logits) {
    extern __shared__ float sm[];
    constexpr int M_BLK = 128, N_BLK = 128, WM = 4, WN = 4, MT = 2, NT = 4;
    float acc[MT][NT][4] = {};
    const int nb = blockIdx.x;
    gemm_acc<M_BLK, N_BLK, WM, WN, MT, NT>(
        g_y, UNITS, oW + nb * N_BLK, VOCAB, UNITS, acc, sm);

    const int lane = threadIdx.x & 31, warp = threadIdx.x >> 5;
    const int wm = warp / WN, wn = warp % WN;
    #pragma unroll
    for (int mt = 0; mt < MT; mt++) {
        int r0 = (wm * MT + mt) * 16 + (lane >> 2);
        #pragma unroll
        for (int nt = 0; nt < NT; nt++) {
            int cg = nb * N_BLK + (wn * NT + nt) * 8 + (lane & 3) * 2;
            logits[(size_t)r0 * VOCAB + cg]           = acc[mt][nt][0] + ob[cg];
            logits[(size_t)r0 * VOCAB + cg + 1]       = acc[mt][nt][1] + ob[cg + 1];
            logits[(size_t)(r0 + 8) * VOCAB + cg]     = acc[mt][nt][2] + ob[cg];
            logits[(size_t)(r0 + 8) * VOCAB + cg + 1] = acc[mt][nt][3] + ob[cg + 1];
        }
    }
}

// ---------------- launch ----------------
extern "C" void kernel_launch(void* const* d_in, const int* in_sizes, int n_in,
                              void* d_out, int out_size) {
    const int*   inputs = (const int*)  d_in[0];
    const float* attn   = (const float*)d_in[1];
    const float* W0     = (const float*)d_in[2];
    const float* b0     = (const float*)d_in[3];
    /* d_in[4] = W1   (dead: hidden0 == 0) */
    const float* b1     = (const float*)d_in[5];
    const float* vW     = (const float*)d_in[6];
    /* d_in[7] = vb   (cancels in softmax) */
    const float* emb    = (const float*)d_in[8];
    const float* gru_k  = (const float*)d_in[9];
    /* d_in[10] = gru_rk (dead: h == 0) */
    const float* gru_b  = (const float*)d_in[11];
    const float* dW     = (const float*)d_in[12];
    const float* db     = (const float*)d_in[13];
    const float* oW     = (const float*)d_in[14];
    const float* ob     = (const float*)d_in[15];

    float* out    = (float*)d_out;
    float* logits = out;
    float* state  = out + (size_t)BATCH * VOCAB;
    float* alpha  = state + BATCH * UNITS;

    // all dynamic smem sizes <= 48 KB default window (no attribute calls)
    const int SM_SCORE  = (2 * 64 * 20 + 2 * 16 * (256 + 4) + SEQ) * 4;   // 43776 B
    const int SM_SMALL  = (2 * 32 * 20 + 2 * 16 * (128 + 4)) * 4;         // 22016 B
    const int SM_LOGITS = (2 * 128 * 20 + 2 * 16 * (128 + 4)) * 4;        // 37376 B

    k_score<<<BATCH, 512, SM_SCORE>>>(attn, W0, b0, b1, vW);
    k_softmax_ctx<<<BATCH, 256>>>(attn, inputs, emb, alpha);
    k_gru_gemm<<<dim3(4, 12), 256, SM_SMALL>>>(gru_k, gru_b);
    k_gates<<<BATCH, UNITS>>>(gru_b, state);
    k_dense<<<dim3(4, 4), 256, SM_SMALL>>>(state, dW, db);
    k_logits<<<250, 512, SM_LOGITS>>>(oW, ob, logits);
}

// round 4
// speedup vs baseline: 1.3752x; 1.3752x over previous
#include <cuda_runtime.h>
#include <cuda_bf16.h>
#include <cstdint>
#include <cstddef>

#define UNITS 512
#define VOCAB 32000
#define BATCH 128
#define SEQ   64

// ---------------- scratch (no allocation allowed) ----------------
__device__ float g_score[BATCH * SEQ];
__device__ float g_xc[BATCH * 2 * UNITS];        // [x (emb) | context]
__device__ float g_preact[BATCH * 3 * UNITS];    // xc @ gru_k + gru_b[0]
__device__ float g_y[BATCH * UNITS];             // relu(state @ dW + db)

// ---------------- bf16 split helpers ----------------
__device__ __forceinline__ void split2(float v0, float v1, uint32_t& hi, uint32_t& lo) {
    __nv_bfloat16 h0 = __float2bfloat16_rn(v0);
    __nv_bfloat16 h1 = __float2bfloat16_rn(v1);
    __nv_bfloat16 l0 = __float2bfloat16_rn(v0 - __bfloat162float(h0));
    __nv_bfloat16 l1 = __float2bfloat16_rn(v1 - __bfloat162float(h1));
    hi = (uint32_t)__bfloat16_as_ushort(h0) | ((uint32_t)__bfloat16_as_ushort(h1) << 16);
    lo = (uint32_t)__bfloat16_as_ushort(l0) | ((uint32_t)__bfloat16_as_ushort(l1) << 16);
}

__device__ __forceinline__ void mma16(float c[4], const uint32_t a[4],
                                      uint32_t b0, uint32_t b1) {
    asm volatile(
        "mma.sync.aligned.m16n8k16.row.col.f32.bf16.bf16.f32 "
        "{%0,%1,%2,%3}, {%4,%5,%6,%7}, {%8,%9}, {%0,%1,%2,%3};"
        : "+f"(c[0]), "+f"(c[1]), "+f"(c[2]), "+f"(c[3])
        : "r"(a[0]), "r"(a[1]), "r"(a[2]), "r"(a[3]), "r"(b0), "r"(b1));
}

// ---------------- 3-pass bf16-split GEMM core ----------------
// acc += A(M_BLK x K) @ B(K x N_BLK), fp32 in gmem, ~fp32 accuracy.
// A row-major (lda), B row-major (ldb, block cols at bn0).
// smem words: A (hi+lo): M_BLK*P*2 ; B (hi+lo): N_BLK*P*2 ; P = 20.
// Each smem word = 2 consecutive-k bf16 (kpair). Fragment loads are
// single LDS.32, quad-conflict-free (banks (20r+qid)%32 distinct).
template <int M_BLK, int N_BLK, int NTHR, int WM, int WN, int MT, int NT>
__device__ __forceinline__ void gemm3_bf16(const float* __restrict__ A, int lda,
                                           const float* __restrict__ B, int ldb, int bn0,
                                           int K, float acc[MT][NT][4], uint32_t* sm32) {
    constexpr int P = 20;     // 16 kpairs + 4 pad
    uint32_t* sAh = sm32;
    uint32_t* sAl = sAh + M_BLK * P;
    uint32_t* sBh = sAl + M_BLK * P;
    uint32_t* sBl = sBh + N_BLK * P;

    const int tid = threadIdx.x, lane = tid & 31, warp = tid >> 5;
    const int wm = warp / WN, wn = warp % WN;
    const int grp = lane >> 2, qid = lane & 3;

    for (int k0 = 0; k0 < K; k0 += 32) {
        // stage A: (row, kpair) -> packed bf16x2 hi/lo
        for (int i = tid; i < M_BLK * 16; i += NTHR) {
            int r = i >> 4, kp = i & 15;
            float2 v = *(const float2*)&A[(size_t)r * lda + k0 + kp * 2];
            uint32_t hi, lo; split2(v.x, v.y, hi, lo);
            sAh[r * P + kp] = hi;
            sAl[r * P + kp] = lo;
        }
        // stage B: read two k-rows (coalesced over n), pack kpairs per col
        for (int i = tid; i < N_BLK * 16; i += NTHR) {
            int kp = i / N_BLK, n = i % N_BLK;
            float v0 = B[(size_t)(k0 + kp * 2)     * ldb + bn0 + n];
            float v1 = B[(size_t)(k0 + kp * 2 + 1) * ldb + bn0 + n];
            uint32_t hi, lo; split2(v0, v1, hi, lo);
            sBh[n * P + kp] = hi;
            sBl[n * P + kp] = lo;
        }
        __syncthreads();

        #pragma unroll
        for (int kk = 0; kk < 2; kk++) {      // two k16 steps per 32-chunk
            const int kp0 = kk * 8 + qid;
            uint32_t ah[MT][4], al[MT][4];
            #pragma unroll
            for (int mt = 0; mt < MT; mt++) {
                int r = (wm * MT + mt) * 16 + grp;
                ah[mt][0] = sAh[r * P + kp0];         al[mt][0] = sAl[r * P + kp0];
                ah[mt][1] = sAh[(r + 8) * P + kp0];   al[mt][1] = sAl[(r + 8) * P + kp0];
                ah[mt][2] = sAh[r * P + kp0 + 4];     al[mt][2] = sAl[r * P + kp0 + 4];
                ah[mt][3] = sAh[(r + 8) * P + kp0 + 4]; al[mt][3] = sAl[(r + 8) * P + kp0 + 4];
            }
            #pragma unroll
            for (int nt = 0; nt < NT; nt++) {
                int n = (wn * NT + nt) * 8 + grp;
                uint32_t bh0 = sBh[n * P + kp0], bh1 = sBh[n * P + kp0 + 4];
                uint32_t bl0 = sBl[n * P + kp0], bl1 = sBl[n * P + kp0 + 4];
                #pragma unroll
                for (int mt = 0; mt < MT; mt++) {
                    mma16(acc[mt][nt], ah[mt], bh0, bh1);   // hi*hi
                    mma16(acc[mt][nt], al[mt], bh0, bh1);   // lo*hi
                    mma16(acc[mt][nt], ah[mt], bl0, bl1);   // hi*lo
                }
            }
        }
        __syncthreads();
    }
}

// ---------------- kernel 1: fused attention-score GEMM ----------------
// score[b,s] = sum_j tanh( (attn[b] @ W0)[s,j] + b0[j] + b1[j] ) * vW[j]
// One block per batch b; 4 N-chunks of 128; full score reduced in-block.
__global__ void __launch_bounds__(512) k_score(const float* __restrict__ attn,
                                               const float* __restrict__ W0,
                                               const float* __restrict__ b0,
                                               const float* __restrict__ b1,
                                               const float* __restrict__ vW) {
    extern __shared__ uint32_t sm32[];
    constexpr int M_BLK = 64, N_BLK = 128, NTHR = 512, WM = 2, WN = 8, MT = 2, NT = 2;
    constexpr int GEMM_W = (M_BLK + N_BLK) * 20 * 2;
    float* sScore = (float*)(sm32 + GEMM_W);

    const int b = blockIdx.x;
    const int tid = threadIdx.x, lane = tid & 31, warp = tid >> 5;
    const int wm = warp / WN, wn = warp % WN;
    const int grp = lane >> 2, qid = lane & 3;

    if (tid < SEQ) sScore[tid] = 0.f;

    float rs[MT][2] = {};
    for (int nc = 0; nc < UNITS / N_BLK; nc++) {
        __syncthreads();
        float acc[MT][NT][4] = {};
        gemm3_bf16<M_BLK, N_BLK, NTHR, WM, WN, MT, NT>(
            attn + (size_t)b * SEQ * UNITS, UNITS, W0, UNITS, nc * N_BLK, UNITS, acc, sm32);

        #pragma unroll
        for (int mt = 0; mt < MT; mt++) {
            #pragma unroll
            for (int nt = 0; nt < NT; nt++) {
                int c0 = nc * N_BLK + (wn * NT + nt) * 8 + qid * 2;
                float bia0 = __ldg(&b0[c0]) + __ldg(&b1[c0]);
                float bia1 = __ldg(&b0[c0 + 1]) + __ldg(&b1[c0 + 1]);
                float v0 = __ldg(&vW[c0]), v1 = __ldg(&vW[c0 + 1]);
                rs[mt][0] += tanhf(acc[mt][nt][0] + bia0) * v0 + tanhf(acc[mt][nt][1] + bia1) * v1;
                rs[mt][1] += tanhf(acc[mt][nt][2] + bia0) * v0 + tanhf(acc[mt][nt][3] + bia1) * v1;
            }
        }
    }
    // reduce over qid, then across warps via smem atomics
    #pragma unroll
    for (int mt = 0; mt < MT; mt++) {
        #pragma unroll
        for (int h = 0; h < 2; h++) {
            float v = rs[mt][h];
            v += __shfl_xor_sync(0xffffffffu, v, 1);
            v += __shfl_xor_sync(0xffffffffu, v, 2);
            if (qid == 0) {
                int r = (wm * MT + mt) * 16 + h * 8 + grp;
                atomicAdd(&sScore[r], v);
            }
        }
    }
    __syncthreads();
    if (tid < SEQ) g_score[b * SEQ + tid] = sScore[tid];
}

// ---------------- kernel 2: softmax + context + embedding gather ------
__global__ void __launch_bounds__(256) k_softmax_ctx(const float* __restrict__ attn,
                                                     const int* __restrict__ inputs,
                                                     const float* __restrict__ emb,
                                                     float* __restrict__ alpha_out) {
    __shared__ float sA[SEQ];
    __shared__ float sRed;
    const int b = blockIdx.x, tid = threadIdx.x;

    if (tid < SEQ) sA[tid] = g_score[b * SEQ + tid];
    __syncthreads();
    if (tid == 0) {
        float m = sA[0];
        for (int i = 1; i < SEQ; i++) m = fmaxf(m, sA[i]);
        sRed = m;
    }
    __syncthreads();
    if (tid < SEQ) sA[tid] = expf(sA[tid] - sRed);
    __syncthreads();
    if (tid == 0) {
        float s = 0.f;
        for (int i = 0; i < SEQ; i++) s += sA[i];
        sRed = s;
    }
    __syncthreads();
    if (tid < SEQ) {
        sA[tid] = sA[tid] / sRed;
        alpha_out[b * SEQ + tid] = sA[tid];
    }
    __syncthreads();

    const int idx = inputs[b];
    for (int u = tid; u < UNITS; u += 256) {
        float accv = 0.f;
        const float* ap = attn + (size_t)b * SEQ * UNITS + u;
        #pragma unroll 8
        for (int s = 0; s < SEQ; s++) accv += sA[s] * ap[s * UNITS];
        g_xc[b * 2 * UNITS + UNITS + u] = accv;                     // context
        g_xc[b * 2 * UNITS + u] = emb[(size_t)idx * UNITS + u];     // emb gather
    }
}

// ---------------- kernel 3: GRU input GEMM ----------------
// preact[:, n0:n0+64] = xc @ gru_k[:, n0:n0+64] + gru_b[0, n0:n0+64]
__global__ void __launch_bounds__(256) k_gru(const float* __restrict__ gru_k,
                                             const float* __restrict__ gru_b) {
    extern __shared__ uint32_t sm32[];
    constexpr int M_BLK = 128, N_BLK = 64, NTHR = 256, WM = 4, WN = 2, MT = 2, NT = 4;
    const int n0 = blockIdx.x * N_BLK;   // 24 blocks

    float acc[MT][NT][4] = {};
    gemm3_bf16<M_BLK, N_BLK, NTHR, WM, WN, MT, NT>(
        g_xc, 2 * UNITS, gru_k, 3 * UNITS, n0, 2 * UNITS, acc, sm32);

    const int lane = threadIdx.x & 31, warp = threadIdx.x >> 5;
    const int wm = warp / WN, wn = warp % WN;
    const int grp = lane >> 2, qid = lane & 3;
    #pragma unroll
    for (int mt = 0; mt < MT; mt++) {
        int r = (wm * MT + mt) * 16 + grp;
        #pragma unroll
        for (int nt = 0; nt < NT; nt++) {
            int c = n0 + (wn * NT + nt) * 8 + qid * 2;
            float bb0 = __ldg(&gru_b[c]), bb1 = __ldg(&gru_b[c + 1]);
            g_preact[r * 3 * UNITS + c]           = acc[mt][nt][0] + bb0;
            g_preact[r * 3 * UNITS + c + 1]       = acc[mt][nt][1] + bb1;
            g_preact[(r + 8) * 3 * UNITS + c]     = acc[mt][nt][2] + bb0;
            g_preact[(r + 8) * 3 * UNITS + c + 1] = acc[mt][nt][3] + bb1;
        }
    }
}

// ---------------- kernel 4: GRU gate combine (h == 0) ----------------
__global__ void __launch_bounds__(512) k_gates(const float* __restrict__ gru_b,
                                               float* __restrict__ state) {
    const int b = blockIdx.x, u = threadIdx.x;
    const float* p = g_preact + b * 3 * UNITS;
    const float* gb1 = gru_b + 3 * UNITS;   // gru_b[1]
    float xz = p[u], xr = p[UNITS + u], xh = p[2 * UNITS + u];
    float z = 1.f / (1.f + expf(-(xz + gb1[u])));
    float r = 1.f / (1.f + expf(-(xr + gb1[UNITS + u])));
    float hh = tanhf(xh + r * gb1[2 * UNITS + u]);
    state[b * UNITS + u] = (1.f - z) * hh;   // z*h vanishes (h==0)
}

// ---------------- kernel 5: dense layer ----------------
__global__ void __launch_bounds__(256) k_dense(const float* __restrict__ state,
                                               const float* __restrict__ dW,
                                               const float* __restrict__ db) {
    extern __shared__ uint32_t sm32[];
    constexpr int M_BLK = 128, N_BLK = 64, NTHR = 256, WM = 4, WN = 2, MT = 2, NT = 4;
    const int n0 = blockIdx.x * N_BLK;   // 8 blocks

    float acc[MT][NT][4] = {};
    gemm3_bf16<M_BLK, N_BLK, NTHR, WM, WN, MT, NT>(
        state, UNITS, dW, UNITS, n0, UNITS, acc, sm32);

    const int lane = threadIdx.x & 31, warp = threadIdx.x >> 5;
    const int wm = warp / WN, wn = warp % WN;
    const int grp = lane >> 2, qid = lane & 3;
    #pragma unroll
    for (int mt = 0; mt < MT; mt++) {
        int r = (wm * MT + mt) * 16 + grp;
        #pragma unroll
        for (int nt = 0; nt < NT; nt++) {
            int c = n0 + (wn * NT + nt) * 8 + qid * 2;
            float bb0 = __ldg(&db[c]), bb1 = __ldg(&db[c + 1]);
            g_y[r * UNITS + c]           = fmaxf(acc[mt][nt][0] + bb0, 0.f);
            g_y[r * UNITS + c + 1]       = fmaxf(acc[mt][nt][1] + bb1, 0.f);
            g_y[(r + 8) * UNITS + c]     = fmaxf(acc[mt][nt][2] + bb0, 0.f);
            g_y[(r + 8) * UNITS + c + 1] = fmaxf(acc[mt][nt][3] + bb1, 0.f);
        }
    }
}

// ---------------- kernel 6: vocab projection ----------------
// logits = y @ oW + ob ; full batch per block -> oW streamed exactly once.
__global__ void __launch_bounds__(256) k_logits(const float* __restrict__ oW,
                                                const float* __restrict__ ob,
                                                float* __restrict__ logits) {
    extern __shared__ uint32_t sm32[];
    constexpr int M_BLK = 128, N_BLK = 128, NTHR = 256, WM = 4, WN = 2, MT = 2, NT = 8;
    const int n0 = blockIdx.x * N_BLK;   // 250 blocks

    float acc[MT][NT][4] = {};
    gemm3_bf16<M_BLK, N_BLK, NTHR, WM, WN, MT, NT>(
        g_y, UNITS, oW, VOCAB, n0, UNITS, acc, sm32);

    const int lane = threadIdx.x & 31, warp = threadIdx.x >> 5;
    const int wm = warp / WN, wn = warp % WN;
    const int grp = lane >> 2, qid = lane & 3;
    #pragma unroll
    for (int mt = 0; mt < MT; mt++) {
        int r = (wm * MT + mt) * 16 + grp;
        #pragma unroll
        for (int nt = 0; nt < NT; nt++) {
            int c = n0 + (wn * NT + nt) * 8 + qid * 2;
            float bb0 = __ldg(&ob[c]), bb1 = __ldg(&ob[c + 1]);
            logits[(size_t)r * VOCAB + c]           = acc[mt][nt][0] + bb0;
            logits[(size_t)r * VOCAB + c + 1]       = acc[mt][nt][1] + bb1;
            logits[(size_t)(r + 8) * VOCAB + c]     = acc[mt][nt][2] + bb0;
            logits[(size_t)(r + 8) * VOCAB + c + 1] = acc[mt][nt][3] + bb1;
        }
    }
}

// ---------------- launch ----------------
extern "C" void kernel_launch(void* const* d_in, const int* in_sizes, int n_in,
                              void* d_out, int out_size) {
    const int*   inputs = (const int*)  d_in[0];
    const float* attn   = (const float*)d_in[1];
    const float* W0     = (const float*)d_in[2];
    const float* b0     = (const float*)d_in[3];
    /* d_in[4] = W1   (dead: hidden0 == 0) */
    const float* b1     = (const float*)d_in[5];
    const float* vW     = (const float*)d_in[6];
    /* d_in[7] = vb   (cancels in softmax) */
    const float* emb    = (const float*)d_in[8];
    const float* gru_k  = (const float*)d_in[9];
    /* d_in[10] = gru_rk (dead: h == 0) */
    const float* gru_b  = (const float*)d_in[11];
    const float* dW     = (const float*)d_in[12];
    const float* db     = (const float*)d_in[13];
    const float* oW     = (const float*)d_in[14];
    const float* ob     = (const float*)d_in[15];

    float* out    = (float*)d_out;
    float* logits = out;
    float* state  = out + (size_t)BATCH * VOCAB;
    float* alpha  = state + BATCH * UNITS;

    // dynamic smem (bytes); all <= 48 KB default window
    const int SM_SCORE  = ((64 + 128) * 40 + SEQ) * 4;   // 30976
    const int SM_SMALL  = ((128 + 64) * 40) * 4;         // 30720
    const int SM_LOGITS = ((128 + 128) * 40) * 4;        // 40960

    k_score<<<BATCH, 512, SM_SCORE>>>(attn, W0, b0, b1, vW);
    k_softmax_ctx<<<BATCH, 256>>>(attn, inputs, emb, alpha);
    k_gru<<<24, 256, SM_SMALL>>>(gru_k, gru_b);
    k_gates<<<BATCH, UNITS>>>(gru_b, state);
    k_dense<<<8, 256, SM_SMALL>>>(state, dW, db);
    k_logits<<<250, 256, SM_LOGITS>>>(oW, ob, logits);
}

// round 5
// speedup vs baseline: 2.1688x; 1.5770x over previous
#include <cuda_runtime.h>
#include <cuda_fp16.h>
#include <cstdint>
#include <cstddef>

#define UNITS 512
#define VOCAB 32000
#define BATCH 128
#define SEQ   64

// ---------------- scratch (no allocation allowed) ----------------
__device__ float g_score[BATCH * SEQ];
__device__ float g_xc[BATCH * 2 * UNITS];        // [x (emb) | context]
__device__ float g_preact[BATCH * 3 * UNITS];    // xc @ gru_k + gru_b[0]
__device__ float g_y[BATCH * UNITS];             // relu(state @ dW + db)

// pre-split weights, transposed to [n][kpair] packed fp16x2
__device__ uint32_t g_W0t   [512  * 256];
__device__ uint32_t g_grukt_h[1536 * 512];
__device__ uint32_t g_grukt_l[1536 * 512];
__device__ uint32_t g_dWt_h [512  * 256];
__device__ uint32_t g_dWt_l [512  * 256];
__device__ uint32_t g_oWt   [32000 * 256];

// ---------------- helpers ----------------
__device__ __forceinline__ uint32_t packh(__half a, __half b) {
    return (uint32_t)__half_as_ushort(a) | ((uint32_t)__half_as_ushort(b) << 16);
}

__device__ __forceinline__ void splith(float v0, float v1, uint32_t& hi, uint32_t& lo) {
    __half h0 = __float2half_rn(v0), h1 = __float2half_rn(v1);
    __half l0 = __float2half_rn(v0 - __half2float(h0));
    __half l1 = __float2half_rn(v1 - __half2float(h1));
    hi = packh(h0, h1);
    lo = packh(l0, l1);
}

__device__ __forceinline__ void mma16(float c[4], const uint32_t a[4],
                                      uint32_t b0, uint32_t b1) {
    asm volatile(
        "mma.sync.aligned.m16n8k16.row.col.f32.f16.f16.f32 "
        "{%0,%1,%2,%3}, {%4,%5,%6,%7}, {%8,%9}, {%0,%1,%2,%3};"
        : "+f"(c[0]), "+f"(c[1]), "+f"(c[2]), "+f"(c[3])
        : "r"(a[0]), "r"(a[1]), "r"(a[2]), "r"(a[3]), "r"(b0), "r"(b1));
}

// ---------------- weight transpose + fp16-split conversion ----------------
// W: [K, N] fp32 row-major  ->  oh/ol: [N, K/2] packed fp16x2 (kpair-major)
__global__ void __launch_bounds__(256) k_conv(const float* __restrict__ W,
                                              uint32_t* __restrict__ oh,
                                              uint32_t* __restrict__ ol,
                                              int K, int N) {
    __shared__ float s[64][65];
    const int tid = threadIdx.x;
    const int n0 = blockIdx.x * 64, k0 = blockIdx.y * 64;
    for (int i = tid; i < 64 * 64; i += 256) {
        int r = i >> 6, c = i & 63;
        s[r][c] = W[(size_t)(k0 + r) * N + n0 + c];
    }
    __syncthreads();
    const int Kp = K >> 1;
    for (int i = tid; i < 64 * 32; i += 256) {
        int n = i >> 5, kp = i & 31;
        float v0 = s[2 * kp][n], v1 = s[2 * kp + 1][n];
        __half h0 = __float2half_rn(v0), h1 = __float2half_rn(v1);
        size_t o = (size_t)(n0 + n) * Kp + (k0 >> 1) + kp;
        oh[o] = packh(h0, h1);
        if (ol) {
            __half l0 = __float2half_rn(v0 - __half2float(h0));
            __half l1 = __float2half_rn(v1 - __half2float(h1));
            ol[o] = packh(l0, l1);
        }
    }
}

// ---------------- fp16-split GEMM core ----------------
// acc += A(M_BLK x K fp32) @ B(K x N_BLK, pre-split fp16 kpair-packed).
// PASSES=2: Ah*Bh + Al*Bh   (err ~ B quant, 2^-11)
// PASSES=3: + Ah*Bl         (err ~ 2^-21)
template <int M_BLK, int N_BLK, int NTHR, int WM, int WN, int MT, int NT, int PASSES>
__device__ __forceinline__ void gemm_f16(const float* __restrict__ A, int lda,
                                         const uint32_t* __restrict__ Bh,
                                         const uint32_t* __restrict__ Bl, int ldb_kp,
                                         int K, float acc[MT][NT][4], uint32_t* sm32) {
    constexpr int P = 20;      // 16 kpairs + 4 pad
    uint32_t* sAh = sm32;
    uint32_t* sAl = sAh + M_BLK * P;
    uint32_t* sBh = sAl + M_BLK * P;
    uint32_t* sBl = sBh + N_BLK * P;   // used only when PASSES==3

    const int tid = threadIdx.x, lane = tid & 31, warp = tid >> 5;
    const int wm = warp / WN, wn = warp % WN;
    const int grp = lane >> 2, qid = lane & 3;

    for (int k0 = 0; k0 < K; k0 += 32) {
        // stage A (split fp32 -> fp16 hi/lo, packed kpairs)
        for (int i = tid; i < M_BLK * 16; i += NTHR) {
            int r = i >> 4, kp = i & 15;
            float2 v = *(const float2*)&A[(size_t)r * lda + k0 + kp * 2];
            uint32_t hi, lo; splith(v.x, v.y, hi, lo);
            sAh[r * P + kp] = hi;
            sAl[r * P + kp] = lo;
        }
        // stage B (pure uint4 copy of pre-split weights)
        for (int i = tid * 4; i < N_BLK * 16; i += NTHR * 4) {
            int n = i >> 4, kp = i & 15;
            size_t src = (size_t)n * ldb_kp + (k0 >> 1) + kp;
            *(uint4*)&sBh[n * P + kp] = *(const uint4*)&Bh[src];
            if (PASSES == 3)
                *(uint4*)&sBl[n * P + kp] = *(const uint4*)&Bl[src];
        }
        __syncthreads();

        #pragma unroll
        for (int kk = 0; kk < 2; kk++) {
            const int kp0 = kk * 8 + qid;
            uint32_t ah[MT][4], al[MT][4];
            #pragma unroll
            for (int mt = 0; mt < MT; mt++) {
                int r = (wm * MT + mt) * 16 + grp;
                ah[mt][0] = sAh[r * P + kp0];           al[mt][0] = sAl[r * P + kp0];
                ah[mt][1] = sAh[(r + 8) * P + kp0];     al[mt][1] = sAl[(r + 8) * P + kp0];
                ah[mt][2] = sAh[r * P + kp0 + 4];       al[mt][2] = sAl[r * P + kp0 + 4];
                ah[mt][3] = sAh[(r + 8) * P + kp0 + 4]; al[mt][3] = sAl[(r + 8) * P + kp0 + 4];
            }
            #pragma unroll
            for (int nt = 0; nt < NT; nt++) {
                int n = (wn * NT + nt) * 8 + grp;
                uint32_t bh0 = sBh[n * P + kp0], bh1 = sBh[n * P + kp0 + 4];
                #pragma unroll
                for (int mt = 0; mt < MT; mt++) {
                    mma16(acc[mt][nt], ah[mt], bh0, bh1);   // hi*B
                    mma16(acc[mt][nt], al[mt], bh0, bh1);   // lo*B
                }
                if (PASSES == 3) {
                    uint32_t bl0 = sBl[n * P + kp0], bl1 = sBl[n * P + kp0 + 4];
                    #pragma unroll
                    for (int mt = 0; mt < MT; mt++)
                        mma16(acc[mt][nt], ah[mt], bl0, bl1);   // hi*Bl
                }
            }
        }
        __syncthreads();
    }
}

// ---------------- kernel 1: fused attention-score GEMM ----------------
// score[b,s] = sum_j tanh( (attn[b] @ W0)[s,j] + b0[j] + b1[j] ) * vW[j]
__global__ void __launch_bounds__(512) k_score(const float* __restrict__ attn,
                                               const float* __restrict__ b0,
                                               const float* __restrict__ b1,
                                               const float* __restrict__ vW) {
    extern __shared__ uint32_t sm32[];
    constexpr int M_BLK = 64, N_BLK = 128, NTHR = 512, WM = 2, WN = 8, MT = 2, NT = 2;
    constexpr int GEMM_W = M_BLK * 20 * 2 + N_BLK * 20;   // 5120 words
    float* sScore = (float*)(sm32 + GEMM_W);

    const int b = blockIdx.x;
    const int tid = threadIdx.x, lane = tid & 31, warp = tid >> 5;
    const int wm = warp / WN, wn = warp % WN;
    const int grp = lane >> 2, qid = lane & 3;

    if (tid < SEQ) sScore[tid] = 0.f;

    float rs[MT][2] = {};
    for (int nc = 0; nc < UNITS / N_BLK; nc++) {
        float acc[MT][NT][4] = {};
        gemm_f16<M_BLK, N_BLK, NTHR, WM, WN, MT, NT, 2>(
            attn + (size_t)b * SEQ * UNITS, UNITS,
            g_W0t + (size_t)nc * N_BLK * 256, g_W0t, 256, UNITS, acc, sm32);

        #pragma unroll
        for (int mt = 0; mt < MT; mt++) {
            #pragma unroll
            for (int nt = 0; nt < NT; nt++) {
                int c0 = nc * N_BLK + (wn * NT + nt) * 8 + qid * 2;
                float bia0 = __ldg(&b0[c0]) + __ldg(&b1[c0]);
                float bia1 = __ldg(&b0[c0 + 1]) + __ldg(&b1[c0 + 1]);
                float v0 = __ldg(&vW[c0]), v1 = __ldg(&vW[c0 + 1]);
                rs[mt][0] += tanhf(acc[mt][nt][0] + bia0) * v0 + tanhf(acc[mt][nt][1] + bia1) * v1;
                rs[mt][1] += tanhf(acc[mt][nt][2] + bia0) * v0 + tanhf(acc[mt][nt][3] + bia1) * v1;
            }
        }
    }
    #pragma unroll
    for (int mt = 0; mt < MT; mt++) {
        #pragma unroll
        for (int h = 0; h < 2; h++) {
            float v = rs[mt][h];
            v += __shfl_xor_sync(0xffffffffu, v, 1);
            v += __shfl_xor_sync(0xffffffffu, v, 2);
            if (qid == 0) {
                int r = (wm * MT + mt) * 16 + h * 8 + grp;
                atomicAdd(&sScore[r], v);
            }
        }
    }
    __syncthreads();
    if (tid < SEQ) g_score[b * SEQ + tid] = sScore[tid];
}

// ---------------- kernel 2: softmax + context + embedding gather ------
__global__ void __launch_bounds__(256) k_softmax_ctx(const float* __restrict__ attn,
                                                     const int* __restrict__ inputs,
                                                     const float* __restrict__ emb,
                                                     float* __restrict__ alpha_out) {
    __shared__ float sA[SEQ];
    __shared__ float sRed;
    const int b = blockIdx.x, tid = threadIdx.x;

    if (tid < SEQ) sA[tid] = g_score[b * SEQ + tid];
    __syncthreads();
    if (tid == 0) {
        float m = sA[0];
        for (int i = 1; i < SEQ; i++) m = fmaxf(m, sA[i]);
        sRed = m;
    }
    __syncthreads();
    if (tid < SEQ) sA[tid] = expf(sA[tid] - sRed);
    __syncthreads();
    if (tid == 0) {
        float s = 0.f;
        for (int i = 0; i < SEQ; i++) s += sA[i];
        sRed = s;
    }
    __syncthreads();
    if (tid < SEQ) {
        sA[tid] = sA[tid] / sRed;
        alpha_out[b * SEQ + tid] = sA[tid];
    }
    __syncthreads();

    const int idx = inputs[b];
    for (int u = tid; u < UNITS; u += 256) {
        float accv = 0.f;
        const float* ap = attn + (size_t)b * SEQ * UNITS + u;
        #pragma unroll 8
        for (int s = 0; s < SEQ; s++) accv += sA[s] * ap[s * UNITS];
        g_xc[b * 2 * UNITS + UNITS + u] = accv;                     // context
        g_xc[b * 2 * UNITS + u] = emb[(size_t)idx * UNITS + u];     // emb gather
    }
}

// ---------------- kernel 3: GRU input GEMM (3-pass) ----------------
__global__ void __launch_bounds__(256) k_gru(const float* __restrict__ gru_b) {
    extern __shared__ uint32_t sm32[];
    constexpr int M_BLK = 64, N_BLK = 64, NTHR = 256, WM = 2, WN = 4, MT = 2, NT = 2;
    const int n0 = blockIdx.x * N_BLK;   // 24
    const int m0 = blockIdx.y * M_BLK;   // 2

    float acc[MT][NT][4] = {};
    gemm_f16<M_BLK, N_BLK, NTHR, WM, WN, MT, NT, 3>(
        g_xc + (size_t)m0 * 2 * UNITS, 2 * UNITS,
        g_grukt_h + (size_t)n0 * 512, g_grukt_l + (size_t)n0 * 512, 512,
        2 * UNITS, acc, sm32);

    const int lane = threadIdx.x & 31, warp = threadIdx.x >> 5;
    const int wm = warp / WN, wn = warp % WN;
    const int grp = lane >> 2, qid = lane & 3;
    #pragma unroll
    for (int mt = 0; mt < MT; mt++) {
        int r = m0 + (wm * MT + mt) * 16 + grp;
        #pragma unroll
        for (int nt = 0; nt < NT; nt++) {
            int c = n0 + (wn * NT + nt) * 8 + qid * 2;
            float bb0 = __ldg(&gru_b[c]), bb1 = __ldg(&gru_b[c + 1]);
            g_preact[r * 3 * UNITS + c]           = acc[mt][nt][0] + bb0;
            g_preact[r * 3 * UNITS + c + 1]       = acc[mt][nt][1] + bb1;
            g_preact[(r + 8) * 3 * UNITS + c]     = acc[mt][nt][2] + bb0;
            g_preact[(r + 8) * 3 * UNITS + c + 1] = acc[mt][nt][3] + bb1;
        }
    }
}

// ---------------- kernel 4: GRU gate combine (h == 0) ----------------
__global__ void __launch_bounds__(512) k_gates(const float* __restrict__ gru_b,
                                               float* __restrict__ state) {
    const int b = blockIdx.x, u = threadIdx.x;
    const float* p = g_preact + b * 3 * UNITS;
    const float* gb1 = gru_b + 3 * UNITS;   // gru_b[1]
    float xz = p[u], xr = p[UNITS + u], xh = p[2 * UNITS + u];
    float z = 1.f / (1.f + expf(-(xz + gb1[u])));
    float r = 1.f / (1.f + expf(-(xr + gb1[UNITS + u])));
    float hh = tanhf(xh + r * gb1[2 * UNITS + u]);
    state[b * UNITS + u] = (1.f - z) * hh;   // z*h vanishes (h==0)
}

// ---------------- kernel 5: dense layer (3-pass) ----------------
__global__ void __launch_bounds__(256) k_dense(const float* __restrict__ state,
                                               const float* __restrict__ db) {
    extern __shared__ uint32_t sm32[];
    constexpr int M_BLK = 64, N_BLK = 64, NTHR = 256, WM = 2, WN = 4, MT = 2, NT = 2;
    const int n0 = blockIdx.x * N_BLK;   // 8
    const int m0 = blockIdx.y * M_BLK;   // 2

    float acc[MT][NT][4] = {};
    gemm_f16<M_BLK, N_BLK, NTHR, WM, WN, MT, NT, 3>(
        state + (size_t)m0 * UNITS, UNITS,
        g_dWt_h + (size_t)n0 * 256, g_dWt_l + (size_t)n0 * 256, 256,
        UNITS, acc, sm32);

    const int lane = threadIdx.x & 31, warp = threadIdx.x >> 5;
    const int wm = warp / WN, wn = warp % WN;
    const int grp = lane >> 2, qid = lane & 3;
    #pragma unroll
    for (int mt = 0; mt < MT; mt++) {
        int r = m0 + (wm * MT + mt) * 16 + grp;
        #pragma unroll
        for (int nt = 0; nt < NT; nt++) {
            int c = n0 + (wn * NT + nt) * 8 + qid * 2;
            float bb0 = __ldg(&db[c]), bb1 = __ldg(&db[c + 1]);
            g_y[r * UNITS + c]           = fmaxf(acc[mt][nt][0] + bb0, 0.f);
            g_y[r * UNITS + c + 1]       = fmaxf(acc[mt][nt][1] + bb1, 0.f);
            g_y[(r + 8) * UNITS + c]     = fmaxf(acc[mt][nt][2] + bb0, 0.f);
            g_y[(r + 8) * UNITS + c + 1] = fmaxf(acc[mt][nt][3] + bb1, 0.f);
        }
    }
}

// ---------------- kernel 6: vocab projection (2-pass) ----------------
__global__ void __launch_bounds__(256) k_logits(const float* __restrict__ ob,
                                                float* __restrict__ logits) {
    extern __shared__ uint32_t sm32[];
    constexpr int M_BLK = 128, N_BLK = 128, NTHR = 256, WM = 4, WN = 2, MT = 2, NT = 8;
    const int n0 = blockIdx.x * N_BLK;   // 250 blocks

    float acc[MT][NT][4] = {};
    gemm_f16<M_BLK, N_BLK, NTHR, WM, WN, MT, NT, 2>(
        g_y, UNITS, g_oWt + (size_t)n0 * 256, g_oWt, 256, UNITS, acc, sm32);

    const int lane = threadIdx.x & 31, warp = threadIdx.x >> 5;
    const int wm = warp / WN, wn = warp % WN;
    const int grp = lane >> 2, qid = lane & 3;
    #pragma unroll
    for (int mt = 0; mt < MT; mt++) {
        int r = (wm * MT + mt) * 16 + grp;
        #pragma unroll
        for (int nt = 0; nt < NT; nt++) {
            int c = n0 + (wn * NT + nt) * 8 + qid * 2;
            float bb0 = __ldg(&ob[c]), bb1 = __ldg(&ob[c + 1]);
            logits[(size_t)r * VOCAB + c]           = acc[mt][nt][0] + bb0;
            logits[(size_t)r * VOCAB + c + 1]       = acc[mt][nt][1] + bb1;
            logits[(size_t)(r + 8) * VOCAB + c]     = acc[mt][nt][2] + bb0;
            logits[(size_t)(r + 8) * VOCAB + c + 1] = acc[mt][nt][3] + bb1;
        }
    }
}

// ---------------- launch ----------------
extern "C" void kernel_launch(void* const* d_in, const int* in_sizes, int n_in,
                              void* d_out, int out_size) {
    const int*   inputs = (const int*)  d_in[0];
    const float* attn   = (const float*)d_in[1];
    const float* W0     = (const float*)d_in[2];
    const float* b0     = (const float*)d_in[3];
    /* d_in[4] = W1   (dead: hidden0 == 0) */
    const float* b1     = (const float*)d_in[5];
    const float* vW     = (const float*)d_in[6];
    /* d_in[7] = vb   (cancels in softmax) */
    const float* emb    = (const float*)d_in[8];
    const float* gru_k  = (const float*)d_in[9];
    /* d_in[10] = gru_rk (dead: h == 0) */
    const float* gru_b  = (const float*)d_in[11];
    const float* dW     = (const float*)d_in[12];
    const float* db     = (const float*)d_in[13];
    const float* oW     = (const float*)d_in[14];
    const float* ob     = (const float*)d_in[15];

    float* out    = (float*)d_out;
    float* logits = out;
    float* state  = out + (size_t)BATCH * VOCAB;
    float* alpha  = state + BATCH * UNITS;

    void *pW0t, *pGkh, *pGkl, *pdWh, *pdWl, *poWt;
    cudaGetSymbolAddress(&pW0t, g_W0t);
    cudaGetSymbolAddress(&pGkh, g_grukt_h);
    cudaGetSymbolAddress(&pGkl, g_grukt_l);
    cudaGetSymbolAddress(&pdWh, g_dWt_h);
    cudaGetSymbolAddress(&pdWl, g_dWt_l);
    cudaGetSymbolAddress(&poWt, g_oWt);

    // weight pre-split (runs each replay; deterministic)
    k_conv<<<dim3(8,   8), 256>>>(W0,    (uint32_t*)pW0t, nullptr,          512,  512);
    k_conv<<<dim3(24, 16), 256>>>(gru_k, (uint32_t*)pGkh, (uint32_t*)pGkl, 1024, 1536);
    k_conv<<<dim3(8,   8), 256>>>(dW,    (uint32_t*)pdWh, (uint32_t*)pdWl,  512,  512);
    k_conv<<<dim3(500, 8), 256>>>(oW,    (uint32_t*)poWt, nullptr,          512, 32000);

    // dynamic smem (bytes); all <= 48 KB default window
    const int SM_SCORE  = (64 * 40 + 128 * 20 + SEQ) * 4;  // 20736
    const int SM_SMALL  = (64 * 40 + 64 * 40) * 4;         // 20480
    const int SM_LOGITS = (128 * 40 + 128 * 20) * 4;       // 30720

    k_score<<<BATCH, 512, SM_SCORE>>>(attn, b0, b1, vW);
    k_softmax_ctx<<<BATCH, 256>>>(attn, inputs, emb, alpha);
    k_gru<<<dim3(24, 2), 256, SM_SMALL>>>(gru_b);
    k_gates<<<BATCH, UNITS>>>(gru_b, state);
    k_dense<<<dim3(8, 2), 256, SM_SMALL>>>(state, db);
    k_logits<<<250, 256, SM_LOGITS>>>(ob, logits);
}

// round 7
// speedup vs baseline: 2.5673x; 1.1838x over previous
#include <cuda_runtime.h>
#include <cuda_fp16.h>
#include <cstdint>
#include <cstddef>

#define UNITS 512
#define VOCAB 32000
#define BATCH 128
#define SEQ   64

// ---------------- scratch (no allocation allowed) ----------------
__device__ float g_score[BATCH * SEQ];
__device__ float g_xc[BATCH * 2 * UNITS];        // [x (emb) | context]
__device__ float g_preact[BATCH * 3 * UNITS];    // xc @ gru_k + gru_b[0]
__device__ float g_y[BATCH * UNITS];             // relu(state @ dW + db)

// pre-split weights, transposed to [n][kpair] packed fp16x2 (small mats only)
__device__ uint32_t g_W0t    [512  * 256];
__device__ uint32_t g_grukt_h[1536 * 512];
__device__ uint32_t g_grukt_l[1536 * 512];
__device__ uint32_t g_dWt_h  [512  * 256];
__device__ uint32_t g_dWt_l  [512  * 256];

// ---------------- helpers ----------------
__device__ __forceinline__ uint32_t packh(__half a, __half b) {
    return (uint32_t)__half_as_ushort(a) | ((uint32_t)__half_as_ushort(b) << 16);
}

__device__ __forceinline__ void splith(float v0, float v1, uint32_t& hi, uint32_t& lo) {
    __half h0 = __float2half_rn(v0), h1 = __float2half_rn(v1);
    __half l0 = __float2half_rn(v0 - __half2float(h0));
    __half l1 = __float2half_rn(v1 - __half2float(h1));
    hi = packh(h0, h1);
    lo = packh(l0, l1);
}

__device__ __forceinline__ void mma16(float c[4], const uint32_t a[4],
                                      uint32_t b0, uint32_t b1) {
    asm volatile(
        "mma.sync.aligned.m16n8k16.row.col.f32.f16.f16.f32 "
        "{%0,%1,%2,%3}, {%4,%5,%6,%7}, {%8,%9}, {%0,%1,%2,%3};"
        : "+f"(c[0]), "+f"(c[1]), "+f"(c[2]), "+f"(c[3])
        : "r"(a[0]), "r"(a[1]), "r"(a[2]), "r"(a[3]), "r"(b0), "r"(b1));
}

// ---------------- weight transpose + fp16-split conversion ----------------
// W: [K, N] fp32 row-major  ->  oh/ol: [N, K/2] packed fp16x2 (kpair-major)
__global__ void __launch_bounds__(256) k_conv(const float* __restrict__ W,
                                              uint32_t* __restrict__ oh,
                                              uint32_t* __restrict__ ol,
                                              int K, int N) {
    __shared__ float s[64][65];
    const int tid = threadIdx.x;
    const int n0 = blockIdx.x * 64, k0 = blockIdx.y * 64;
    for (int i = tid; i < 64 * 64; i += 256) {
        int r = i >> 6, c = i & 63;
        s[r][c] = W[(size_t)(k0 + r) * N + n0 + c];
    }
    __syncthreads();
    const int Kp = K >> 1;
    for (int i = tid; i < 64 * 32; i += 256) {
        int n = i >> 5, kp = i & 31;
        float v0 = s[2 * kp][n], v1 = s[2 * kp + 1][n];
        __half h0 = __float2half_rn(v0), h1 = __float2half_rn(v1);
        size_t o = (size_t)(n0 + n) * Kp + (k0 >> 1) + kp;
        oh[o] = packh(h0, h1);
        if (ol) {
            __half l0 = __float2half_rn(v0 - __half2float(h0));
            __half l1 = __float2half_rn(v1 - __half2float(h1));
            ol[o] = packh(l0, l1);
        }
    }
}

// ---------------- fp16 GEMM core (pre-split B) ----------------
// acc += A(M_BLK x K fp32) @ B(K x N_BLK, pre-split fp16 kpair-packed)
// PASSES=1: Ah*Bh          (err ~ A+B quant, ~2^-11 each)
// PASSES=3: + Al*Bh + Ah*Bl (err ~ 2^-21)
template <int M_BLK, int N_BLK, int NTHR, int WM, int WN, int MT, int NT, int PASSES>
__device__ __forceinline__ void gemm_f16(const float* __restrict__ A, int lda,
                                         const uint32_t* __restrict__ Bh,
                                         const uint32_t* __restrict__ Bl, int ldb_kp,
                                         int K, float acc[MT][NT][4], uint32_t* sm32) {
    constexpr int P = 20;      // 16 kpairs + 4 pad
    constexpr bool MP = (PASSES >= 3);
    uint32_t* sAh = sm32;
    uint32_t* sAl = sAh + M_BLK * P;
    uint32_t* sBh = sAl + (MP ? M_BLK * P : 0);
    uint32_t* sBl = sBh + N_BLK * P;

    const int tid = threadIdx.x, lane = tid & 31, warp = tid >> 5;
    const int wm = warp / WN, wn = warp % WN;
    const int grp = lane >> 2, qid = lane & 3;

    for (int k0 = 0; k0 < K; k0 += 32) {
        for (int i = tid; i < M_BLK * 16; i += NTHR) {
            int r = i >> 4, kp = i & 15;
            float2 v = *(const float2*)&A[(size_t)r * lda + k0 + kp * 2];
            if (MP) {
                uint32_t hi, lo; splith(v.x, v.y, hi, lo);
                sAh[r * P + kp] = hi;
                sAl[r * P + kp] = lo;
            } else {
                sAh[r * P + kp] = packh(__float2half_rn(v.x), __float2half_rn(v.y));
            }
        }
        for (int i = tid * 4; i < N_BLK * 16; i += NTHR * 4) {
            int n = i >> 4, kp = i & 15;
            size_t src = (size_t)n * ldb_kp + (k0 >> 1) + kp;
            *(uint4*)&sBh[n * P + kp] = *(const uint4*)&Bh[src];
            if (MP)
                *(uint4*)&sBl[n * P + kp] = *(const uint4*)&Bl[src];
        }
        __syncthreads();

        #pragma unroll
        for (int kk = 0; kk < 2; kk++) {
            const int kp0 = kk * 8 + qid;
            uint32_t ah[MT][4], al[MT][4];
            #pragma unroll
            for (int mt = 0; mt < MT; mt++) {
                int r = (wm * MT + mt) * 16 + grp;
                ah[mt][0] = sAh[r * P + kp0];
                ah[mt][1] = sAh[(r + 8) * P + kp0];
                ah[mt][2] = sAh[r * P + kp0 + 4];
                ah[mt][3] = sAh[(r + 8) * P + kp0 + 4];
                if (MP) {
                    al[mt][0] = sAl[r * P + kp0];
                    al[mt][1] = sAl[(r + 8) * P + kp0];
                    al[mt][2] = sAl[r * P + kp0 + 4];
                    al[mt][3] = sAl[(r + 8) * P + kp0 + 4];
                }
            }
            #pragma unroll
            for (int nt = 0; nt < NT; nt++) {
                int n = (wn * NT + nt) * 8 + grp;
                uint32_t bh0 = sBh[n * P + kp0], bh1 = sBh[n * P + kp0 + 4];
                #pragma unroll
                for (int mt = 0; mt < MT; mt++)
                    mma16(acc[mt][nt], ah[mt], bh0, bh1);
                if (MP) {
                    uint32_t bl0 = sBl[n * P + kp0], bl1 = sBl[n * P + kp0 + 4];
                    #pragma unroll
                    for (int mt = 0; mt < MT; mt++) {
                        mma16(acc[mt][nt], al[mt], bh0, bh1);
                        mma16(acc[mt][nt], ah[mt], bl0, bl1);
                    }
                }
            }
        }
        __syncthreads();
    }
}

// ---------------- kernel 1: fused attention-score GEMM (1-pass) ----------------
__global__ void __launch_bounds__(512) k_score(const float* __restrict__ attn,
                                               const float* __restrict__ b0,
                                               const float* __restrict__ b1,
                                               const float* __restrict__ vW) {
    extern __shared__ uint32_t sm32[];
    constexpr int M_BLK = 64, N_BLK = 128, NTHR = 512, WM = 2, WN = 8, MT = 2, NT = 2;
    constexpr int GEMM_W = M_BLK * 20 + N_BLK * 20;
    float* sScore = (float*)(sm32 + GEMM_W);

    const int b = blockIdx.x;
    const int tid = threadIdx.x, lane = tid & 31, warp = tid >> 5;
    const int wm = warp / WN, wn = warp % WN;
    const int grp = lane >> 2, qid = lane & 3;

    if (tid < SEQ) sScore[tid] = 0.f;

    float rs[MT][2] = {};
    for (int nc = 0; nc < UNITS / N_BLK; nc++) {
        float acc[MT][NT][4] = {};
        gemm_f16<M_BLK, N_BLK, NTHR, WM, WN, MT, NT, 1>(
            attn + (size_t)b * SEQ * UNITS, UNITS,
            g_W0t + (size_t)nc * N_BLK * 256, nullptr, 256, UNITS, acc, sm32);

        #pragma unroll
        for (int mt = 0; mt < MT; mt++) {
            #pragma unroll
            for (int nt = 0; nt < NT; nt++) {
                int c0 = nc * N_BLK + (wn * NT + nt) * 8 + qid * 2;
                float bia0 = __ldg(&b0[c0]) + __ldg(&b1[c0]);
                float bia1 = __ldg(&b0[c0 + 1]) + __ldg(&b1[c0 + 1]);
                float v0 = __ldg(&vW[c0]), v1 = __ldg(&vW[c0 + 1]);
                rs[mt][0] += tanhf(acc[mt][nt][0] + bia0) * v0 + tanhf(acc[mt][nt][1] + bia1) * v1;
                rs[mt][1] += tanhf(acc[mt][nt][2] + bia0) * v0 + tanhf(acc[mt][nt][3] + bia1) * v1;
            }
        }
    }
    #pragma unroll
    for (int mt = 0; mt < MT; mt++) {
        #pragma unroll
        for (int h = 0; h < 2; h++) {
            float v = rs[mt][h];
            v += __shfl_xor_sync(0xffffffffu, v, 1);
            v += __shfl_xor_sync(0xffffffffu, v, 2);
            if (qid == 0) {
                int r = (wm * MT + mt) * 16 + h * 8 + grp;
                atomicAdd(&sScore[r], v);
            }
        }
    }
    __syncthreads();
    if (tid < SEQ) g_score[b * SEQ + tid] = sScore[tid];
}

// ---------------- kernel 2: softmax + context + embedding gather ------
__global__ void __launch_bounds__(256) k_softmax_ctx(const float* __restrict__ attn,
                                                     const int* __restrict__ inputs,
                                                     const float* __restrict__ emb,
                                                     float* __restrict__ alpha_out) {
    __shared__ float sA[SEQ];
    __shared__ float sRed;
    const int b = blockIdx.x, tid = threadIdx.x;

    if (tid < SEQ) sA[tid] = g_score[b * SEQ + tid];
    __syncthreads();
    if (tid == 0) {
        float m = sA[0];
        for (int i = 1; i < SEQ; i++) m = fmaxf(m, sA[i]);
        sRed = m;
    }
    __syncthreads();
    if (tid < SEQ) sA[tid] = expf(sA[tid] - sRed);
    __syncthreads();
    if (tid == 0) {
        float s = 0.f;
        for (int i = 0; i < SEQ; i++) s += sA[i];
        sRed = s;
    }
    __syncthreads();
    if (tid < SEQ) {
        sA[tid] = sA[tid] / sRed;
        alpha_out[b * SEQ + tid] = sA[tid];
    }
    __syncthreads();

    const int idx = inputs[b];
    for (int u = tid; u < UNITS; u += 256) {
        float accv = 0.f;
        const float* ap = attn + (size_t)b * SEQ * UNITS + u;
        #pragma unroll 8
        for (int s = 0; s < SEQ; s++) accv += sA[s] * ap[s * UNITS];
        g_xc[b * 2 * UNITS + UNITS + u] = accv;                     // context
        g_xc[b * 2 * UNITS + u] = emb[(size_t)idx * UNITS + u];     // emb gather
    }
}

// ---------------- kernel 3: GRU input GEMM (3-pass) ----------------
__global__ void __launch_bounds__(256) k_gru(const float* __restrict__ gru_b) {
    extern __shared__ uint32_t sm32[];
    constexpr int M_BLK = 64, N_BLK = 64, NTHR = 256, WM = 2, WN = 4, MT = 2, NT = 2;
    const int n0 = blockIdx.x * N_BLK;
    const int m0 = blockIdx.y * M_BLK;

    float acc[MT][NT][4] = {};
    gemm_f16<M_BLK, N_BLK, NTHR, WM, WN, MT, NT, 3>(
        g_xc + (size_t)m0 * 2 * UNITS, 2 * UNITS,
        g_grukt_h + (size_t)n0 * 512, g_grukt_l + (size_t)n0 * 512, 512,
        2 * UNITS, acc, sm32);

    const int lane = threadIdx.x & 31, warp = threadIdx.x >> 5;
    const int wm = warp / WN, wn = warp % WN;
    const int grp = lane >> 2, qid = lane & 3;
    #pragma unroll
    for (int mt = 0; mt < MT; mt++) {
        int r = m0 + (wm * MT + mt) * 16 + grp;
        #pragma unroll
        for (int nt = 0; nt < NT; nt++) {
            int c = n0 + (wn * NT + nt) * 8 + qid * 2;
            float bb0 = __ldg(&gru_b[c]), bb1 = __ldg(&gru_b[c + 1]);
            g_preact[r * 3 * UNITS + c]           = acc[mt][nt][0] + bb0;
            g_preact[r * 3 * UNITS + c + 1]       = acc[mt][nt][1] + bb1;
            g_preact[(r + 8) * 3 * UNITS + c]     = acc[mt][nt][2] + bb0;
            g_preact[(r + 8) * 3 * UNITS + c + 1] = acc[mt][nt][3] + bb1;
        }
    }
}

// ---------------- kernel 4: GRU gate combine (h == 0) ----------------
__global__ void __launch_bounds__(512) k_gates(const float* __restrict__ gru_b,
                                               float* __restrict__ state) {
    const int b = blockIdx.x, u = threadIdx.x;
    const float* p = g_preact + b * 3 * UNITS;
    const float* gb1 = gru_b + 3 * UNITS;   // gru_b[1]
    float xz = p[u], xr = p[UNITS + u], xh = p[2 * UNITS + u];
    float z = 1.f / (1.f + expf(-(xz + gb1[u])));
    float r = 1.f / (1.f + expf(-(xr + gb1[UNITS + u])));
    float hh = tanhf(xh + r * gb1[2 * UNITS + u]);
    state[b * UNITS + u] = (1.f - z) * hh;   // z*h vanishes (h==0)
}

// ---------------- kernel 5: dense layer (3-pass) ----------------
__global__ void __launch_bounds__(256) k_dense(const float* __restrict__ state,
                                               const float* __restrict__ db) {
    extern __shared__ uint32_t sm32[];
    constexpr int M_BLK = 64, N_BLK = 64, NTHR = 256, WM = 2, WN = 4, MT = 2, NT = 2;
    const int n0 = blockIdx.x * N_BLK;
    const int m0 = blockIdx.y * M_BLK;

    float acc[MT][NT][4] = {};
    gemm_f16<M_BLK, N_BLK, NTHR, WM, WN, MT, NT, 3>(
        state + (size_t)m0 * UNITS, UNITS,
        g_dWt_h + (size_t)n0 * 256, g_dWt_l + (size_t)n0 * 256, 256,
        UNITS, acc, sm32);

    const int lane = threadIdx.x & 31, warp = threadIdx.x >> 5;
    const int wm = warp / WN, wn = warp % WN;
    const int grp = lane >> 2, qid = lane & 3;
    #pragma unroll
    for (int mt = 0; mt < MT; mt++) {
        int r = m0 + (wm * MT + mt) * 16 + grp;
        #pragma unroll
        for (int nt = 0; nt < NT; nt++) {
            int c = n0 + (wn * NT + nt) * 8 + qid * 2;
            float bb0 = __ldg(&db[c]), bb1 = __ldg(&db[c + 1]);
            g_y[r * UNITS + c]           = fmaxf(acc[mt][nt][0] + bb0, 0.f);
            g_y[r * UNITS + c + 1]       = fmaxf(acc[mt][nt][1] + bb1, 0.f);
            g_y[(r + 8) * UNITS + c]     = fmaxf(acc[mt][nt][2] + bb0, 0.f);
            g_y[(r + 8) * UNITS + c + 1] = fmaxf(acc[mt][nt][3] + bb1, 0.f);
        }
    }
}

// ---------------- kernel 6: vocab projection (1-pass, direct oW) ----------------
// logits = y @ oW + ob. Stages oW fp32->fp16 in-kernel: each block owns a
// disjoint 128-col strip, so every oW element is read & converted exactly once.
__global__ void __launch_bounds__(256) k_logits(const float* __restrict__ oW,
                                                const float* __restrict__ ob,
                                                float* __restrict__ logits) {
    extern __shared__ uint32_t sm32[];
    constexpr int M_BLK = 128, N_BLK = 128, NTHR = 256, WM = 4, WN = 2, MT = 2, NT = 8;
    constexpr int P = 20;
    uint32_t* sAh = sm32;
    uint32_t* sBh = sAh + M_BLK * P;

    const int n0 = blockIdx.x * N_BLK;   // 250 blocks
    const int tid = threadIdx.x, lane = tid & 31, warp = tid >> 5;
    const int wm = warp / WN, wn = warp % WN;
    const int grp = lane >> 2, qid = lane & 3;

    float acc[MT][NT][4] = {};
    for (int k0 = 0; k0 < UNITS; k0 += 32) {
        // stage A (y), fp16 hi only
        for (int i = tid; i < M_BLK * 16; i += NTHR) {
            int r = i >> 4, kp = i & 15;
            float2 v = *(const float2*)&g_y[(size_t)r * UNITS + k0 + kp * 2];
            sAh[r * P + kp] = packh(__float2half_rn(v.x), __float2half_rn(v.y));
        }
        // stage B directly from oW fp32 (coalesced over n), convert to fp16
        for (int i = tid; i < N_BLK * 16; i += NTHR) {
            int kp = i >> 7, n = i & 127;
            float v0 = oW[(size_t)(k0 + kp * 2)     * VOCAB + n0 + n];
            float v1 = oW[(size_t)(k0 + kp * 2 + 1) * VOCAB + n0 + n];
            sBh[n * P + kp] = packh(__float2half_rn(v0), __float2half_rn(v1));
        }
        __syncthreads();

        #pragma unroll
        for (int kk = 0; kk < 2; kk++) {
            const int kp0 = kk * 8 + qid;
            uint32_t ah[MT][4];
            #pragma unroll
            for (int mt = 0; mt < MT; mt++) {
                int r = (wm * MT + mt) * 16 + grp;
                ah[mt][0] = sAh[r * P + kp0];
                ah[mt][1] = sAh[(r + 8) * P + kp0];
                ah[mt][2] = sAh[r * P + kp0 + 4];
                ah[mt][3] = sAh[(r + 8) * P + kp0 + 4];
            }
            #pragma unroll
            for (int nt = 0; nt < NT; nt++) {
                int n = (wn * NT + nt) * 8 + grp;
                uint32_t bh0 = sBh[n * P + kp0], bh1 = sBh[n * P + kp0 + 4];
                #pragma unroll
                for (int mt = 0; mt < MT; mt++)
                    mma16(acc[mt][nt], ah[mt], bh0, bh1);
            }
        }
        __syncthreads();
    }

    #pragma unroll
    for (int mt = 0; mt < MT; mt++) {
        int r = (wm * MT + mt) * 16 + grp;
        #pragma unroll
        for (int nt = 0; nt < NT; nt++) {
            int c = n0 + (wn * NT + nt) * 8 + qid * 2;
            float bb0 = __ldg(&ob[c]), bb1 = __ldg(&ob[c + 1]);
            logits[(size_t)r * VOCAB + c]           = acc[mt][nt][0] + bb0;
            logits[(size_t)r * VOCAB + c + 1]       = acc[mt][nt][1] + bb1;
            logits[(size_t)(r + 8) * VOCAB + c]     = acc[mt][nt][2] + bb0;
            logits[(size_t)(r + 8) * VOCAB + c + 1] = acc[mt][nt][3] + bb1;
        }
    }
}

// ---------------- launch ----------------
extern "C" void kernel_launch(void* const* d_in, const int* in_sizes, int n_in,
                              void* d_out, int out_size) {
    const int*   inputs = (const int*)  d_in[0];
    const float* attn   = (const float*)d_in[1];
    const float* W0     = (const float*)d_in[2];
    const float* b0     = (const float*)d_in[3];
    /* d_in[4] = W1   (dead: hidden0 == 0) */
    const float* b1     = (const float*)d_in[5];
    const float* vW     = (const float*)d_in[6];
    /* d_in[7] = vb   (cancels in softmax) */
    const float* emb    = (const float*)d_in[8];
    const float* gru_k  = (const float*)d_in[9];
    /* d_in[10] = gru_rk (dead: h == 0) */
    const float* gru_b  = (const float*)d_in[11];
    const float* dW     = (const float*)d_in[12];
    const float* db     = (const float*)d_in[13];
    const float* oW     = (const float*)d_in[14];
    const float* ob     = (const float*)d_in[15];

    float* out    = (float*)d_out;
    float* logits = out;
    float* state  = out + (size_t)BATCH * VOCAB;
    float* alpha  = state + BATCH * UNITS;

    void *pW0t, *pGkh, *pGkl, *pdWh, *pdWl;
    cudaGetSymbolAddress(&pW0t, g_W0t);
    cudaGetSymbolAddress(&pGkh, g_grukt_h);
    cudaGetSymbolAddress(&pGkl, g_grukt_l);
    cudaGetSymbolAddress(&pdWh, g_dWt_h);
    cudaGetSymbolAddress(&pdWl, g_dWt_l);

    // small-weight pre-split (deterministic; runs each replay)
    k_conv<<<dim3(8,   8), 256>>>(W0,    (uint32_t*)pW0t, nullptr,          512,  512);
    k_conv<<<dim3(24, 16), 256>>>(gru_k, (uint32_t*)pGkh, (uint32_t*)pGkl, 1024, 1536);
    k_conv<<<dim3(8,   8), 256>>>(dW,    (uint32_t*)pdWh, (uint32_t*)pdWl,  512,  512);

    // dynamic smem (bytes)
    const int SM_SCORE  = ((64 + 128) * 20 + SEQ) * 4;     // 15616
    const int SM_SMALL  = (64 * 40 + 64 * 40) * 4;         // 20480
    const int SM_LOGITS = ((128 + 128) * 20) * 4;          // 20480

    k_score<<<BATCH, 512, SM_SCORE>>>(attn, b0, b1, vW);
    k_softmax_ctx<<<BATCH, 256>>>(attn, inputs, emb, alpha);
    k_gru<<<dim3(24, 2), 256, SM_SMALL>>>(gru_b);
    k_gates<<<BATCH, UNITS>>>(gru_b, state);
    k_dense<<<dim3(8, 2), 256, SM_SMALL>>>(state, db);
    k_logits<<<250, 256, SM_LOGITS>>>(oW, ob, logits);
}